// round 2
// baseline (speedup 1.0000x reference)
#include <cuda_runtime.h>
#include <cstddef>

// KitNET_5257039970983 — two-phase staged version.
// Inputs: x(B,100) f32, Wt(10,7,10), hbias_t(10,7), vbias_t(10,10),
//         Wh(7,10), hbias_h(7), vbias_h(10), clusters(10,10) i32
// Output: head_out(B,10) then tails(B,10), fp32.

#define NTILES 10
#define CDIM   10
#define HDIM   7
#define FDIM   100
#define TPB    256
#define RPB    512
#define PCOLS  50          // columns staged per phase (gathered/permuted order)

// ---- smem layout (byte offsets) ----
#define OFF_XS    0                      // u64[256][50]  = 102400 B (also reused for output staging)
#define OFF_WTT   102400                 // u64[10][10][7] (c-major, packed (w,w)) = 5600 B
#define OFF_HBT   108000                 // u64[10][7]   = 560 B
#define OFF_VBT   108560                 // u64[10][10]  = 800 B
#define OFF_WH    109360                 // u64[7][10]   = 560 B
#define OFF_HBH   109984                 // u64[7] (16B-aligned, padded)
#define OFF_VBH   110040                 // u64[10] = 80 B
#define OFF_PERM  110120                 // int[100] = 400 B
#define SMEM_BYTES 110520

typedef unsigned long long u64;

__device__ __forceinline__ u64 fma2(u64 a, u64 b, u64 c) {
    u64 d;
    asm("fma.rn.f32x2 %0, %1, %2, %3;" : "=l"(d) : "l"(a), "l"(b), "l"(c));
    return d;
}
__device__ __forceinline__ u64 pack2(float x, float y) {
    u64 d;
    asm("mov.b64 %0, {%1, %2};" : "=l"(d) : "f"(x), "f"(y));
    return d;
}
__device__ __forceinline__ void unpack2(u64 a, float& x, float& y) {
    asm("mov.b64 {%0, %1}, %2;" : "=f"(x), "=f"(y) : "l"(a));
}

__global__ void __launch_bounds__(TPB, 2) kitnet_kernel(
    const float* __restrict__ x,
    const float* __restrict__ Wt,
    const float* __restrict__ hbt,
    const float* __restrict__ vbt,
    const float* __restrict__ Wh,
    const float* __restrict__ hbh,
    const float* __restrict__ vbh,
    const int*   __restrict__ clusters,
    float* __restrict__ out,
    int B)
{
    extern __shared__ char smem[];
    u64*  xs   = (u64*)(smem + OFF_XS);     // [pair][50], pair = tid
    u64*  wtt  = (u64*)(smem + OFF_WTT);    // [t][c][h]
    u64*  hbt2 = (u64*)(smem + OFF_HBT);
    u64*  vbt2 = (u64*)(smem + OFF_VBT);
    u64*  wh2  = (u64*)(smem + OFF_WH);
    u64*  hbh2 = (u64*)(smem + OFF_HBH);
    u64*  vbh2 = (u64*)(smem + OFF_VBH);
    int*  perm = (int*)(smem + OFF_PERM);

    const int tid   = threadIdx.x;
    const int base  = blockIdx.x * RPB;
    const int nrows = min(RPB, B - base);

    // ---- stage weights: Wt transposed to c-major, everything packed (w,w) ----
    for (int i = tid; i < NTILES*CDIM*HDIM; i += TPB) {
        int t = i / (CDIM*HDIM);
        int q = i - t * (CDIM*HDIM);
        int c = q / HDIM;
        int h = q - c * HDIM;
        float w = Wt[t*HDIM*CDIM + h*CDIM + c];
        ((float2*)wtt)[i] = make_float2(w, w);
    }
    for (int i = tid; i < NTILES*HDIM; i += TPB) { float w = hbt[i]; ((float2*)hbt2)[i] = make_float2(w, w); }
    for (int i = tid; i < NTILES*CDIM; i += TPB) { float w = vbt[i]; ((float2*)vbt2)[i] = make_float2(w, w); }
    for (int i = tid; i < HDIM*NTILES; i += TPB) { float w = Wh[i];  ((float2*)wh2)[i]  = make_float2(w, w); }
    if (tid < HDIM)   { float w = hbh[tid]; ((float2*)hbh2)[tid] = make_float2(w, w); }
    if (tid < NTILES) { float w = vbh[tid]; ((float2*)vbh2)[tid] = make_float2(w, w); }
    for (int i = tid; i < FDIM; i += TPB) perm[i] = clusters[i];

    const u64 NEG1 = pack2(-1.0f, -1.0f);
    u64 tails[NTILES];
    const float* xg = x + (size_t)base * FDIM;
    const u64* xrow = xs + (unsigned)tid * PCOLS;

    __syncthreads();

    #pragma unroll 1
    for (int p = 0; p < 2; ++p) {
        // ---- stage gathered x columns [p*50, p*50+50) for all rows ----
        if (p) __syncthreads();          // everyone done with previous buffer
        {
            const int* pp = perm + p * PCOLS;
            const int ntot = nrows * PCOLS;
            float* xsf = (float*)xs;
            #pragma unroll 4
            for (int i = tid; i < ntot; i += TPB) {
                unsigned row = (unsigned)i / PCOLS;
                unsigned j   = (unsigned)i - row * PCOLS;
                float v = xg[row * FDIM + pp[j]];
                // packed pair layout: (row & 255) is the pair, (row >> 8) the half
                xsf[((row & 255u) * PCOLS + j) * 2 + (row >> 8)] = v;
            }
        }
        __syncthreads();

        // ---- 5 tiles per phase ----
        #pragma unroll 1
        for (int tt = 0; tt < 5; ++tt) {
            const int t = p * 5 + tt;
            u64 xc[CDIM];
            const u64* xp = xrow + tt * CDIM;
            #pragma unroll
            for (int c = 0; c < CDIM; ++c) xc[c] = xp[c];     // 5x LDS.128

            const u64* WT = wtt + t * CDIM * HDIM;            // [c*7+h]
            const u64* hb = hbt2 + t * HDIM;
            u64 z[HDIM];
            #pragma unroll
            for (int h = 0; h < HDIM; ++h) z[h] = hb[h];
            #pragma unroll
            for (int c = 0; c < CDIM; ++c) {
                #pragma unroll
                for (int h = 0; h < HDIM; ++h)
                    z[h] = fma2(xc[c], WT[c*HDIM + h], z[h]);
            }

            const u64* vb = vbt2 + t * CDIM;
            u64 err = pack2(0.0f, 0.0f);
            #pragma unroll
            for (int c = 0; c < CDIM; ++c) {
                u64 o = fma2(xc[c], NEG1, vb[c]);
                #pragma unroll
                for (int h = 0; h < HDIM; ++h)
                    o = fma2(z[h], WT[c*HDIM + h], o);
                err = fma2(o, o, err);
            }

            float e0, e1;
            unpack2(err, e0, e1);
            tails[t] = pack2(0.5f * __logf(e0 * 0.1f), 0.5f * __logf(e1 * 0.1f));
        }
    }

    // ---- head layer: zh = tails @ Wh.T + hbh ; head_out = zh @ Wh + vbh ----
    u64 zh[HDIM];
    #pragma unroll
    for (int h = 0; h < HDIM; ++h) {
        u64 acc = hbh2[h];
        #pragma unroll
        for (int n = 0; n < NTILES; ++n)
            acc = fma2(tails[n], wh2[h*NTILES + n], acc);
        zh[h] = acc;
    }
    u64 ho[NTILES];
    #pragma unroll
    for (int n = 0; n < NTILES; ++n) ho[n] = vbh2[n];
    #pragma unroll
    for (int h = 0; h < HDIM; ++h) {
        #pragma unroll
        for (int n = 0; n < NTILES; ++n)
            ho[n] = fma2(zh[h], wh2[h*NTILES + n], ho[n]);
    }

    // ---- restage outputs through smem (reuse xs) for coalesced stores ----
    __syncthreads();                     // done reading xs
    float* sh = (float*)smem;            // [row][21]: 0-9 head, 10-19 tails, 21 stride (odd)
    {
        const bool v0 = (tid < nrows);
        const bool v1 = (tid + TPB < nrows);
        float* s0 = sh + tid * 21;
        float* s1 = sh + (tid + TPB) * 21;
        #pragma unroll
        for (int n = 0; n < NTILES; ++n) {
            float a, b; unpack2(ho[n], a, b);
            float ta, tb; unpack2(tails[n], ta, tb);
            if (v0) { s0[n] = a; s0[10 + n] = ta; }
            if (v1) { s1[n] = b; s1[10 + n] = tb; }
        }
    }
    __syncthreads();
    {
        const size_t toff = (size_t)B * NTILES;
        float* oh = out + (size_t)base * NTILES;
        float* ot = out + toff + (size_t)base * NTILES;
        const int ntot = nrows * NTILES;
        #pragma unroll 4
        for (int i = tid; i < ntot; i += TPB) {
            unsigned row = (unsigned)i / NTILES;
            unsigned n   = (unsigned)i - row * NTILES;
            oh[i] = sh[row * 21 + n];
            ot[i] = sh[row * 21 + 10 + n];
        }
    }
}

extern "C" void kernel_launch(void* const* d_in, const int* in_sizes, int n_in,
                              void* d_out, int out_size)
{
    const float* x   = (const float*)d_in[0];
    const float* Wt  = (const float*)d_in[1];
    const float* hbt = (const float*)d_in[2];
    const float* vbt = (const float*)d_in[3];
    const float* Wh  = (const float*)d_in[4];
    const float* hbh = (const float*)d_in[5];
    const float* vbh = (const float*)d_in[6];
    const int*   cls = (const int*)d_in[7];

    const int B = in_sizes[0] / FDIM;
    const int grid = (B + RPB - 1) / RPB;

    cudaFuncSetAttribute(kitnet_kernel, cudaFuncAttributeMaxDynamicSharedMemorySize, SMEM_BYTES);
    kitnet_kernel<<<grid, TPB, SMEM_BYTES>>>(x, Wt, hbt, vbt, Wh, hbh, vbh, cls,
                                             (float*)d_out, B);
}

// round 3
// speedup vs baseline: 2.6051x; 2.6051x over previous
#include <cuda_runtime.h>
#include <cstddef>

// KitNET_5257039970983 — tile-streaming, folded-matrix (M = W^T W - I) version.
// Inputs: x(B,100) f32, Wt(10,7,10), hbias_t(10,7), vbias_t(10,10),
//         Wh(7,10), hbias_h(7), vbias_h(10), clusters(10,10) i32
// Output: head_out(B,10) then tails(B,10), fp32.

#define NTILES 10
#define CDIM   10
#define HDIM   7
#define FDIM   100
#define TPB    256
#define RPB    512            // rows per block; thread packs rows (tid, tid+256)
#define XSTR   11             // u64 stride per pair-row (odd -> conflict-free LDS.64)

// ---- smem layout (byte offsets, 16B aligned) ----
#define OFF_X0    0                       // u64[256][11] = 22528
#define OFF_X1    22528                   // u64[256][11] = 22528
#define OFF_MT    45056                   // u64[10][10][10] = 8000   M_t[t][co][ci] packed (m,m)
#define OFF_BT    53056                   // u64[10][10]     = 800
#define OFF_MH    53856                   // u64[10][10]     = 800    MH[j][i]
#define OFF_BH    54656                   // u64[10]         = 80
#define OFF_PERM  54736                   // int[100]        = 400
#define OFF_TBASE 55136                   // int[10]         = 40
#define SMEM_BYTES 55200

typedef unsigned long long u64;

__device__ __forceinline__ u64 fma2(u64 a, u64 b, u64 c) {
    u64 d;
    asm("fma.rn.f32x2 %0, %1, %2, %3;" : "=l"(d) : "l"(a), "l"(b), "l"(c));
    return d;
}
__device__ __forceinline__ u64 pack2(float x, float y) {
    u64 d;
    asm("mov.b64 %0, {%1, %2};" : "=l"(d) : "f"(x), "f"(y));
    return d;
}
__device__ __forceinline__ void unpack2(u64 a, float& x, float& y) {
    asm("mov.b64 {%0, %1}, %2;" : "=f"(x), "=f"(y) : "l"(a));
}

// stage 10 gathered columns of tile (base/pp) into interleaved pair buffer
__device__ __forceinline__ void stage_tile(const float* __restrict__ xg,
                                           float* __restrict__ xbf,
                                           const int* __restrict__ pp,
                                           int tbase, int nrows, int tid)
{
    if (tbase >= 0) {                       // contiguous, even base: float2 path
        const int ntot = nrows * 5;
        #pragma unroll 2
        for (int i = tid; i < ntot; i += TPB) {
            unsigned row = (unsigned)i / 5u;
            unsigned k   = (unsigned)i - row * 5u;
            float2 v = *(const float2*)(xg + row * FDIM + (unsigned)tbase + 2u * k);
            unsigned p = row & 255u, h = row >> 8;
            unsigned f = (p * XSTR + 2u * k) * 2u + h;
            xbf[f]     = v.x;
            xbf[f + 2] = v.y;
        }
    } else {                                // generic gather
        const int ntot = nrows * 10;
        #pragma unroll 2
        for (int i = tid; i < ntot; i += TPB) {
            unsigned row = (unsigned)i / 10u;
            unsigned j   = (unsigned)i - row * 10u;
            float v = xg[row * FDIM + (unsigned)pp[j]];
            unsigned p = row & 255u, h = row >> 8;
            xbf[(p * XSTR + j) * 2u + h] = v;
        }
    }
}

// err = xc @ M_t + b_t ; return packed sum of squares
__device__ __forceinline__ u64 compute_tile(const u64* __restrict__ xrow,
                                            const u64* __restrict__ Mt,
                                            const u64* __restrict__ bt)
{
    u64 xc[CDIM];
    #pragma unroll
    for (int c = 0; c < CDIM; ++c) xc[c] = xrow[c];
    u64 sq = 0ull;                           // (0.0f, 0.0f)
    #pragma unroll
    for (int co = 0; co < CDIM; ++co) {
        u64 a = bt[co];
        #pragma unroll
        for (int ci = 0; ci < CDIM; ++ci)
            a = fma2(xc[ci], Mt[co * CDIM + ci], a);
        sq = fma2(a, a, sq);
    }
    return sq;
}

__global__ void __launch_bounds__(TPB, 3) kitnet_kernel(
    const float* __restrict__ x,
    const float* __restrict__ Wt,
    const float* __restrict__ hbt,
    const float* __restrict__ vbt,
    const float* __restrict__ Wh,
    const float* __restrict__ hbh,
    const float* __restrict__ vbh,
    const int*   __restrict__ clusters,
    float* __restrict__ out,
    int B)
{
    extern __shared__ char smem[];
    u64* xb[2] = { (u64*)(smem + OFF_X0), (u64*)(smem + OFF_X1) };
    u64* MT    = (u64*)(smem + OFF_MT);
    u64* BT    = (u64*)(smem + OFF_BT);
    u64* MH    = (u64*)(smem + OFF_MH);
    u64* BH    = (u64*)(smem + OFF_BH);
    int* perm  = (int*)(smem + OFF_PERM);
    int* tbase = (int*)(smem + OFF_TBASE);

    const int tid   = threadIdx.x;
    const int base  = blockIdx.x * RPB;
    const int nrows = min(RPB, B - base);
    const float* xg = x + (size_t)base * FDIM;

    // ---- prologue P1: raw weights -> scratch (in X1 region), perm, stage tile 0 ----
    float* scr = (float*)(smem + OFF_X1);    // 957 floats << 22528 B
    float* sW   = scr;          // [10][7][10]
    float* sHB  = scr + 700;    // [10][7]
    float* sVB  = scr + 770;    // [10][10]
    float* sWH  = scr + 870;    // [7][10]
    float* sHBH = scr + 940;    // [7]
    float* sVBH = scr + 947;    // [10]
    for (int i = tid; i < 700; i += TPB) sW[i]  = Wt[i];
    for (int i = tid; i < 70;  i += TPB) sHB[i] = hbt[i];
    for (int i = tid; i < 100; i += TPB) sVB[i] = vbt[i];
    for (int i = tid; i < 70;  i += TPB) sWH[i] = Wh[i];
    if (tid < HDIM)   sHBH[tid] = hbh[tid];
    if (tid < NTILES) sVBH[tid] = vbh[tid];
    for (int i = tid; i < FDIM; i += TPB) perm[i] = clusters[i];
    // stage tile 0 using global clusters directly (generic path, L1-cached)
    {
        const int ntot = nrows * 10;
        float* xbf = (float*)xb[0];
        for (int i = tid; i < ntot; i += TPB) {
            unsigned row = (unsigned)i / 10u;
            unsigned j   = (unsigned)i - row * 10u;
            float v = xg[row * FDIM + (unsigned)clusters[j]];
            unsigned p = row & 255u, h = row >> 8;
            xbf[(p * XSTR + j) * 2u + h] = v;
        }
    }
    __syncthreads();

    // ---- prologue P2: fold matrices ----
    for (int i = tid; i < NTILES * CDIM * CDIM; i += TPB) {   // 1000 entries
        int t  = i / 100;
        int r  = i - t * 100;
        int co = r / 10;
        int ci = r - co * 10;
        float m = (ci == co) ? -1.0f : 0.0f;
        #pragma unroll
        for (int h = 0; h < HDIM; ++h)
            m += sW[t * 70 + h * 10 + ci] * sW[t * 70 + h * 10 + co];
        ((float2*)MT)[i] = make_float2(m, m);
    }
    for (int i = tid; i < NTILES * CDIM; i += TPB) {          // b_t
        int t = i / 10, c = i - t * 10;
        float b = sVB[i];
        #pragma unroll
        for (int h = 0; h < HDIM; ++h)
            b += sHB[t * HDIM + h] * sW[t * 70 + h * 10 + c];
        ((float2*)BT)[i] = make_float2(b, b);
    }
    for (int i = tid; i < CDIM * CDIM; i += TPB) {            // MH[j][i]
        int j = i / 10, ii = i - j * 10;
        float m = 0.0f;
        #pragma unroll
        for (int h = 0; h < HDIM; ++h)
            m += sWH[h * 10 + ii] * sWH[h * 10 + j];
        ((float2*)MH)[i] = make_float2(m, m);
    }
    if (tid < NTILES) {                                       // b_h
        float b = sVBH[tid];
        #pragma unroll
        for (int h = 0; h < HDIM; ++h)
            b += sHBH[h] * sWH[h * 10 + tid];
        ((float2*)BH)[tid] = make_float2(b, b);
    }
    if (tid < NTILES) {                                       // contiguity fast-path
        const int* pp = perm + tid * 10;
        int b0 = pp[0];
        bool ok = ((b0 & 1) == 0);
        #pragma unroll
        for (int j = 1; j < 10; ++j) ok = ok && (pp[j] == b0 + j);
        tbase[tid] = ok ? b0 : -1;
    }
    __syncthreads();

    // ---- main loop: stage t+1 (other buffer) overlapped with compute t ----
    const u64* xr0 = xb[0] + (unsigned)tid * XSTR;
    const u64* xr1 = xb[1] + (unsigned)tid * XSTR;
    u64 tails[NTILES];

    #pragma unroll 1
    for (int t = 0; t < NTILES; ++t) {
        if (t < NTILES - 1)
            stage_tile(xg, (float*)xb[(t + 1) & 1], perm + (t + 1) * 10,
                       tbase[t + 1], nrows, tid);
        u64 sq = compute_tile((t & 1) ? xr1 : xr0, MT + t * 100, BT + t * 10);
        float e0, e1;
        unpack2(sq, e0, e1);
        tails[t] = pack2(0.5f * __logf(e0 * 0.1f), 0.5f * __logf(e1 * 0.1f));
        __syncthreads();
    }

    // ---- head: head_out = tails @ MH^T + b_h ----
    u64 ho[NTILES];
    #pragma unroll
    for (int j = 0; j < NTILES; ++j) {
        u64 a = BH[j];
        #pragma unroll
        for (int i = 0; i < NTILES; ++i)
            a = fma2(tails[i], MH[j * 10 + i], a);
        ho[j] = a;
    }

    // ---- restage outputs through smem (reuse X0/X1) for coalesced stores ----
    float* sh = (float*)smem;                 // [row][21]: 0-9 head, 10-19 tails
    {
        const bool v0 = (tid < nrows);
        const bool v1 = (tid + TPB < nrows);
        float* s0 = sh + tid * 21;
        float* s1 = sh + (tid + TPB) * 21;
        #pragma unroll
        for (int n = 0; n < NTILES; ++n) {
            float a, b;   unpack2(ho[n], a, b);
            float ta, tb; unpack2(tails[n], ta, tb);
            if (v0) { s0[n] = a; s0[10 + n] = ta; }
            if (v1) { s1[n] = b; s1[10 + n] = tb; }
        }
    }
    __syncthreads();
    {
        const size_t toff = (size_t)B * NTILES;
        float* oh = out + (size_t)base * NTILES;
        float* ot = out + toff + (size_t)base * NTILES;
        const int ntot = nrows * NTILES;
        #pragma unroll 4
        for (int i = tid; i < ntot; i += TPB) {
            unsigned row = (unsigned)i / 10u;
            unsigned n   = (unsigned)i - row * 10u;
            oh[i] = sh[row * 21 + n];
            ot[i] = sh[row * 21 + 10 + n];
        }
    }
}

extern "C" void kernel_launch(void* const* d_in, const int* in_sizes, int n_in,
                              void* d_out, int out_size)
{
    const float* x   = (const float*)d_in[0];
    const float* Wt  = (const float*)d_in[1];
    const float* hbt = (const float*)d_in[2];
    const float* vbt = (const float*)d_in[3];
    const float* Wh  = (const float*)d_in[4];
    const float* hbh = (const float*)d_in[5];
    const float* vbh = (const float*)d_in[6];
    const int*   cls = (const int*)d_in[7];

    const int B = in_sizes[0] / FDIM;
    const int grid = (B + RPB - 1) / RPB;

    cudaFuncSetAttribute(kitnet_kernel, cudaFuncAttributeMaxDynamicSharedMemorySize, SMEM_BYTES);
    kitnet_kernel<<<grid, TPB, SMEM_BYTES>>>(x, Wt, hbt, vbt, Wh, hbh, vbh, cls,
                                             (float*)d_out, B);
}